// round 1
// baseline (speedup 1.0000x reference)
#include <cuda_runtime.h>
#include <cstdint>

#define NN 100000
#define FF 128
#define EE 1600000

// Scratch (static device arrays — no allocation APIs allowed)
__device__ float g_h[(size_t)NN * FF];    // layer output before aggregation
__device__ float g_agg[(size_t)NN * FF];  // layer-0 aggregation buffer
__device__ float g_dinv[NN];              // deg then dinv

// ---------------------------------------------------------------------------
// Degree / dinv
// ---------------------------------------------------------------------------
__global__ void k_deg_init(int n) {
    int i = blockIdx.x * blockDim.x + threadIdx.x;
    if (i < n) g_dinv[i] = 1.0f;  // +1 self loop
}

__global__ void k_deg_count(const int* __restrict__ col, int e) {
    int i = blockIdx.x * blockDim.x + threadIdx.x;
    if (i < e) atomicAdd(&g_dinv[col[i]], 1.0f);
}

__global__ void k_dinv(int n) {
    int i = blockIdx.x * blockDim.x + threadIdx.x;
    if (i < n) g_dinv[i] = rsqrtf(g_dinv[i]);
}

// ---------------------------------------------------------------------------
// GEMM: Hout[n,128] = act(A)[n,128] @ W[128,128] + b
// Also writes Aggout = dinv^2 * Hout (self-loop init for aggregation).
// Block: 64 rows, 256 threads; thread (r8 = (t>>5)*8, c = t&31) computes an
// 8x4 micro-tile. K split into 2 chunks of 64 to stay within 48KB smem.
// ---------------------------------------------------------------------------
template <bool RELU_IN>
__global__ void k_gemm(const float* __restrict__ A,
                       const float* __restrict__ W,
                       const float* __restrict__ b,
                       float* __restrict__ Hout,
                       float* __restrict__ Aggout,
                       int n) {
    __shared__ float As[64][64];    // 16KB: A tile (rows x k-chunk)
    __shared__ float Ws[64][128];   // 32KB: W chunk (k-chunk x cols)

    const int t = threadIdx.x;
    const int row0 = blockIdx.x * 64;
    const int c = t & 31;           // col group: cols [4c, 4c+4)
    const int r8 = (t >> 5) * 8;    // row group: rows [r8, r8+8)

    float acc[8][4];
#pragma unroll
    for (int i = 0; i < 8; i++)
#pragma unroll
        for (int j = 0; j < 4; j++) acc[i][j] = 0.0f;

    for (int kc = 0; kc < 2; kc++) {
        // Load W chunk: rows [kc*64, kc*64+64) of W, 2048 float4s
        {
            const float4* Wv = (const float4*)W;
            float4* Wsv = (float4*)&Ws[0][0];
            int base = kc * 64 * 32;
#pragma unroll
            for (int j = 0; j < 8; j++) {
                int idx = t + j * 256;  // 0..2047
                Wsv[idx] = Wv[base + idx];
            }
        }
        // Load A tile: 64 rows x 64 cols chunk = 1024 float4s
        {
#pragma unroll
            for (int j = 0; j < 4; j++) {
                int idx = t + j * 256;      // 0..1023
                int r = idx >> 4;           // row in tile
                int cc = idx & 15;          // float4 within chunk
                int grow = row0 + r;
                float4 v = make_float4(0.f, 0.f, 0.f, 0.f);
                if (grow < n) v = ((const float4*)A)[(size_t)grow * 32 + kc * 16 + cc];
                if (RELU_IN) {
                    v.x = fmaxf(v.x, 0.f); v.y = fmaxf(v.y, 0.f);
                    v.z = fmaxf(v.z, 0.f); v.w = fmaxf(v.w, 0.f);
                }
                ((float4*)&As[r][0])[cc] = v;
            }
        }
        __syncthreads();

#pragma unroll 8
        for (int k = 0; k < 64; k++) {
            float4 w = ((const float4*)&Ws[k][0])[c];
#pragma unroll
            for (int i = 0; i < 8; i++) {
                float a = As[r8 + i][k];
                acc[i][0] = fmaf(a, w.x, acc[i][0]);
                acc[i][1] = fmaf(a, w.y, acc[i][1]);
                acc[i][2] = fmaf(a, w.z, acc[i][2]);
                acc[i][3] = fmaf(a, w.w, acc[i][3]);
            }
        }
        __syncthreads();
    }

    float4 bias = ((const float4*)b)[c];
#pragma unroll
    for (int i = 0; i < 8; i++) {
        int grow = row0 + r8 + i;
        if (grow < n) {
            float4 o;
            o.x = acc[i][0] + bias.x;
            o.y = acc[i][1] + bias.y;
            o.z = acc[i][2] + bias.z;
            o.w = acc[i][3] + bias.w;
            ((float4*)Hout)[(size_t)grow * 32 + c] = o;
            float d = g_dinv[grow];
            float d2 = d * d;
            float4 g;
            g.x = o.x * d2; g.y = o.y * d2; g.z = o.z * d2; g.w = o.w * d2;
            ((float4*)Aggout)[(size_t)grow * 32 + c] = g;
        }
    }
}

// ---------------------------------------------------------------------------
// Edge scatter: agg[row] += dinv[row]*dinv[col] * h[col]
// One warp per edge, one float4 per lane, red.global.add.v4.f32
// ---------------------------------------------------------------------------
__global__ void k_scatter(const int* __restrict__ row,
                          const int* __restrict__ col,
                          const float* __restrict__ h,
                          float* __restrict__ agg,
                          int e) {
    int warp = (blockIdx.x * blockDim.x + threadIdx.x) >> 5;
    int lane = threadIdx.x & 31;
    if (warp >= e) return;
    int r = row[warp];
    int cj = col[warp];
    float coef = g_dinv[r] * g_dinv[cj];
    float4 v = ((const float4*)h)[(size_t)cj * 32 + lane];
    float4 m;
    m.x = v.x * coef; m.y = v.y * coef; m.z = v.z * coef; m.w = v.w * coef;
    float* dst = agg + (size_t)r * 128 + lane * 4;
    asm volatile("red.global.add.v4.f32 [%0], {%1, %2, %3, %4};"
                 :: "l"(dst), "f"(m.x), "f"(m.y), "f"(m.z), "f"(m.w)
                 : "memory");
}

// ---------------------------------------------------------------------------
// log_softmax in place, one warp per row
// ---------------------------------------------------------------------------
__global__ void k_log_softmax(float* __restrict__ out, int n) {
    int warp = (blockIdx.x * blockDim.x + threadIdx.x) >> 5;
    int lane = threadIdx.x & 31;
    if (warp >= n) return;
    float4 v = ((const float4*)out)[(size_t)warp * 32 + lane];
    float mx = fmaxf(fmaxf(v.x, v.y), fmaxf(v.z, v.w));
#pragma unroll
    for (int o = 16; o; o >>= 1) mx = fmaxf(mx, __shfl_xor_sync(0xffffffffu, mx, o));
    float s = expf(v.x - mx) + expf(v.y - mx) + expf(v.z - mx) + expf(v.w - mx);
#pragma unroll
    for (int o = 16; o; o >>= 1) s += __shfl_xor_sync(0xffffffffu, s, o);
    float lse = mx + logf(s);
    v.x -= lse; v.y -= lse; v.z -= lse; v.w -= lse;
    ((float4*)out)[(size_t)warp * 32 + lane] = v;
}

// ---------------------------------------------------------------------------
// Launch
// ---------------------------------------------------------------------------
extern "C" void kernel_launch(void* const* d_in, const int* in_sizes, int n_in,
                              void* d_out, int out_size) {
    const float* x  = (const float*)d_in[0];
    const float* W0 = (const float*)d_in[1];
    const float* b0 = (const float*)d_in[2];
    const float* W1 = (const float*)d_in[3];
    const float* b1 = (const float*)d_in[4];
    const int* row  = (const int*)d_in[5];
    const int* col  = (const int*)d_in[6];
    float* out = (float*)d_out;

    const int n = in_sizes[0] / FF;   // 100000
    const int e = in_sizes[5];        // 1600000

    float* h;   cudaGetSymbolAddress((void**)&h,   g_h);
    float* agg; cudaGetSymbolAddress((void**)&agg, g_agg);

    // degree -> dinv
    k_deg_init<<<(n + 255) / 256, 256>>>(n);
    k_deg_count<<<(e + 255) / 256, 256>>>(col, e);
    k_dinv<<<(n + 255) / 256, 256>>>(n);

    const int gemm_blocks = (n + 63) / 64;
    const int scat_blocks = (e * 32 + 255) / 256;  // one warp per edge

    // Layer 0: h = x@W0+b0 ; agg = dinv^2*h ; agg += scatter
    k_gemm<false><<<gemm_blocks, 256>>>(x, W0, b0, h, agg, n);
    k_scatter<<<scat_blocks, 256>>>(row, col, h, agg, e);

    // Layer 1: h = relu(agg)@W1+b1 ; out = dinv^2*h ; out += scatter ; logsoftmax
    k_gemm<true><<<gemm_blocks, 256>>>(agg, W1, b1, h, out, n);
    k_scatter<<<scat_blocks, 256>>>(row, col, h, out, e);

    k_log_softmax<<<(n * 32 + 255) / 256, 256>>>(out, n);
}

// round 2
// speedup vs baseline: 1.1398x; 1.1398x over previous
#include <cuda_runtime.h>
#include <cstdint>

#define NN 100000
#define FF 128
#define EE 1600000

// Scratch (static device arrays — no allocation APIs allowed)
__device__ float g_hs[(size_t)NN * FF];    // dinv * (A@W + b)
__device__ float g_agg[(size_t)NN * FF];   // layer-0 aggregation result
__device__ float g_dinv[NN];
__device__ int   g_rowcnt[NN];
__device__ int   g_colcnt[NN];
__device__ int   g_rowstart[NN + 1];
__device__ int   g_cursor[NN];
__device__ int   g_colidx[EE];

// ---------------------------------------------------------------------------
// CSR build + degrees
// ---------------------------------------------------------------------------
__global__ void k_zero_counts(int n) {
    int i = blockIdx.x * blockDim.x + threadIdx.x;
    if (i < n) { g_rowcnt[i] = 0; g_colcnt[i] = 0; }
}

__global__ void k_hist(const int* __restrict__ row, const int* __restrict__ col, int e) {
    int i = blockIdx.x * blockDim.x + threadIdx.x;
    if (i < e) {
        atomicAdd(&g_rowcnt[row[i]], 1);
        atomicAdd(&g_colcnt[col[i]], 1);
    }
}

__global__ void k_dinv(int n) {
    int i = blockIdx.x * blockDim.x + threadIdx.x;
    if (i < n) g_dinv[i] = rsqrtf((float)g_colcnt[i] + 1.0f);
}

// Single-block exclusive scan of g_rowcnt -> g_rowstart (and g_cursor copy).
__global__ void k_scan(int n) {
    __shared__ int sums[1024];
    const int t = threadIdx.x;
    const int chunk = (n + 1023) >> 10;
    const int begin = t * chunk;
    const int end = min(begin + chunk, n);

    int s = 0;
    for (int i = begin; i < end; i++) s += g_rowcnt[i];
    sums[t] = s;
    __syncthreads();

    // Hillis-Steele inclusive scan
    for (int off = 1; off < 1024; off <<= 1) {
        int v = (t >= off) ? sums[t - off] : 0;
        __syncthreads();
        sums[t] += v;
        __syncthreads();
    }
    int base = sums[t] - s;  // exclusive prefix

    for (int i = begin; i < end; i++) {
        g_rowstart[i] = base;
        g_cursor[i] = base;
        base += g_rowcnt[i];
    }
    if (begin < n && end == n) g_rowstart[n] = base;
}

__global__ void k_fill(const int* __restrict__ row, const int* __restrict__ col, int e) {
    int i = blockIdx.x * blockDim.x + threadIdx.x;
    if (i < e) {
        int r = row[i];
        int pos = atomicAdd(&g_cursor[r], 1);
        g_colidx[pos] = col[i];
    }
}

// ---------------------------------------------------------------------------
// GEMM: hs[n,128] = dinv * (act(A)[n,128] @ W[128,128] + b)
// ---------------------------------------------------------------------------
template <bool RELU_IN>
__global__ void k_gemm(const float* __restrict__ A,
                       const float* __restrict__ W,
                       const float* __restrict__ b,
                       float* __restrict__ HSout,
                       int n) {
    __shared__ float As[64][64];    // 16KB
    __shared__ float Ws[64][128];   // 32KB

    const int t = threadIdx.x;
    const int row0 = blockIdx.x * 64;
    const int c = t & 31;
    const int r8 = (t >> 5) * 8;

    float acc[8][4];
#pragma unroll
    for (int i = 0; i < 8; i++)
#pragma unroll
        for (int j = 0; j < 4; j++) acc[i][j] = 0.0f;

    for (int kc = 0; kc < 2; kc++) {
        {
            const float4* Wv = (const float4*)W;
            float4* Wsv = (float4*)&Ws[0][0];
            int base = kc * 64 * 32;
#pragma unroll
            for (int j = 0; j < 8; j++) {
                int idx = t + j * 256;
                Wsv[idx] = Wv[base + idx];
            }
        }
        {
#pragma unroll
            for (int j = 0; j < 4; j++) {
                int idx = t + j * 256;
                int r = idx >> 4;
                int cc = idx & 15;
                int grow = row0 + r;
                float4 v = make_float4(0.f, 0.f, 0.f, 0.f);
                if (grow < n) v = ((const float4*)A)[(size_t)grow * 32 + kc * 16 + cc];
                if (RELU_IN) {
                    v.x = fmaxf(v.x, 0.f); v.y = fmaxf(v.y, 0.f);
                    v.z = fmaxf(v.z, 0.f); v.w = fmaxf(v.w, 0.f);
                }
                ((float4*)&As[r][0])[cc] = v;
            }
        }
        __syncthreads();

#pragma unroll 8
        for (int k = 0; k < 64; k++) {
            float4 w = ((const float4*)&Ws[k][0])[c];
#pragma unroll
            for (int i = 0; i < 8; i++) {
                float a = As[r8 + i][k];
                acc[i][0] = fmaf(a, w.x, acc[i][0]);
                acc[i][1] = fmaf(a, w.y, acc[i][1]);
                acc[i][2] = fmaf(a, w.z, acc[i][2]);
                acc[i][3] = fmaf(a, w.w, acc[i][3]);
            }
        }
        __syncthreads();
    }

    float4 bias = ((const float4*)b)[c];
#pragma unroll
    for (int i = 0; i < 8; i++) {
        int grow = row0 + r8 + i;
        if (grow < n) {
            float d = g_dinv[grow];
            float4 o;
            o.x = (acc[i][0] + bias.x) * d;
            o.y = (acc[i][1] + bias.y) * d;
            o.z = (acc[i][2] + bias.z) * d;
            o.w = (acc[i][3] + bias.w) * d;
            ((float4*)HSout)[(size_t)grow * 32 + c] = o;
        }
    }
}

// ---------------------------------------------------------------------------
// Gather: out[i] = dinv[i] * (hs[i] + sum_{j in N(i)} hs[j])
// One warp per row; each lane owns one float4 (4 of 128 features).
// ---------------------------------------------------------------------------
__global__ void k_gather(const float* __restrict__ hs,
                         float* __restrict__ out,
                         int n) {
    int warp = (blockIdx.x * blockDim.x + threadIdx.x) >> 5;
    int lane = threadIdx.x & 31;
    if (warp >= n) return;

    int s = g_rowstart[warp];
    int t_ = g_rowstart[warp + 1];

    float4 acc = ((const float4*)hs)[(size_t)warp * 32 + lane];  // self loop

    for (int e0 = s; e0 < t_; e0 += 32) {
        int j = 0;
        if (e0 + lane < t_) j = g_colidx[e0 + lane];
        int cnt = min(32, t_ - e0);
        for (int k = 0; k < cnt; k++) {
            int jj = __shfl_sync(0xffffffffu, j, k);
            float4 v = ((const float4*)hs)[(size_t)jj * 32 + lane];
            acc.x += v.x; acc.y += v.y; acc.z += v.z; acc.w += v.w;
        }
    }

    float d = g_dinv[warp];
    acc.x *= d; acc.y *= d; acc.z *= d; acc.w *= d;
    ((float4*)out)[(size_t)warp * 32 + lane] = acc;
}

// ---------------------------------------------------------------------------
// log_softmax in place, one warp per row
// ---------------------------------------------------------------------------
__global__ void k_log_softmax(float* __restrict__ out, int n) {
    int warp = (blockIdx.x * blockDim.x + threadIdx.x) >> 5;
    int lane = threadIdx.x & 31;
    if (warp >= n) return;
    float4 v = ((const float4*)out)[(size_t)warp * 32 + lane];
    float mx = fmaxf(fmaxf(v.x, v.y), fmaxf(v.z, v.w));
#pragma unroll
    for (int o = 16; o; o >>= 1) mx = fmaxf(mx, __shfl_xor_sync(0xffffffffu, mx, o));
    float s = expf(v.x - mx) + expf(v.y - mx) + expf(v.z - mx) + expf(v.w - mx);
#pragma unroll
    for (int o = 16; o; o >>= 1) s += __shfl_xor_sync(0xffffffffu, s, o);
    float lse = mx + logf(s);
    v.x -= lse; v.y -= lse; v.z -= lse; v.w -= lse;
    ((float4*)out)[(size_t)warp * 32 + lane] = v;
}

// ---------------------------------------------------------------------------
// Launch
// ---------------------------------------------------------------------------
extern "C" void kernel_launch(void* const* d_in, const int* in_sizes, int n_in,
                              void* d_out, int out_size) {
    const float* x  = (const float*)d_in[0];
    const float* W0 = (const float*)d_in[1];
    const float* b0 = (const float*)d_in[2];
    const float* W1 = (const float*)d_in[3];
    const float* b1 = (const float*)d_in[4];
    const int* row  = (const int*)d_in[5];
    const int* col  = (const int*)d_in[6];
    float* out = (float*)d_out;

    const int n = in_sizes[0] / FF;   // 100000
    const int e = in_sizes[5];        // 1600000

    float* hs;  cudaGetSymbolAddress((void**)&hs,  g_hs);
    float* agg; cudaGetSymbolAddress((void**)&agg, g_agg);

    // Degrees + CSR build (reused by both layers)
    k_zero_counts<<<(n + 255) / 256, 256>>>(n);
    k_hist<<<(e + 255) / 256, 256>>>(row, col, e);
    k_dinv<<<(n + 255) / 256, 256>>>(n);
    k_scan<<<1, 1024>>>(n);
    k_fill<<<(e + 255) / 256, 256>>>(row, col, e);

    const int gemm_blocks = (n + 63) / 64;
    const int gath_blocks = (n * 32 + 255) / 256;  // one warp per row

    // Layer 0
    k_gemm<false><<<gemm_blocks, 256>>>(x, W0, b0, hs, n);
    k_gather<<<gath_blocks, 256>>>(hs, agg, n);

    // Layer 1
    k_gemm<true><<<gemm_blocks, 256>>>(agg, W1, b1, hs, n);
    k_gather<<<gath_blocks, 256>>>(hs, out, n);

    k_log_softmax<<<(n * 32 + 255) / 256, 256>>>(out, n);
}

// round 3
// speedup vs baseline: 1.6153x; 1.4171x over previous
#include <cuda_runtime.h>
#include <cstdint>

#define NN 100000
#define FF 128
#define EE 1600000

// Scratch (static device arrays — no allocation APIs allowed)
__device__ float g_hs[(size_t)NN * FF];    // dinv * (A@W + b)
__device__ float g_agg[(size_t)NN * FF];   // layer-0 aggregation result
__device__ float g_dinv[NN];
__device__ int   g_rowcnt[NN + 4];         // +pad for int4 tail
__device__ int   g_colcnt[NN];
__device__ int   g_rowstart[NN + 1];
__device__ int   g_cursor[NN];
__device__ int   g_colidx[EE];
__device__ int   g_bsums[256];

// ---------------------------------------------------------------------------
// CSR build + degrees
// ---------------------------------------------------------------------------
__global__ void k_zero_counts(int n) {
    int i = blockIdx.x * blockDim.x + threadIdx.x;
    if (i < n + 4) { g_rowcnt[i] = 0; if (i < n) g_colcnt[i] = 0; }
}

__global__ void k_hist(const int* __restrict__ row, const int* __restrict__ col, int e) {
    int i = blockIdx.x * blockDim.x + threadIdx.x;
    if (i < e) {
        atomicAdd(&g_rowcnt[row[i]], 1);
        atomicAdd(&g_colcnt[col[i]], 1);
    }
}

__global__ void k_dinv(int n) {
    int i = blockIdx.x * blockDim.x + threadIdx.x;
    if (i < n) g_dinv[i] = rsqrtf((float)g_colcnt[i] + 1.0f);
}

// --- 3-phase exclusive scan of g_rowcnt -> g_rowstart ---
// Phase 1: per-block (1024 elems) local scan + block sums
__global__ void k_scan_partial(int n) {
    __shared__ int ts[256];
    const int t = threadIdx.x;
    const int base = blockIdx.x * 1024 + t * 4;

    int4 v = make_int4(0, 0, 0, 0);
    if (base < n) v = *(const int4*)&g_rowcnt[base];  // g_rowcnt padded to n+4

    int s = v.x + v.y + v.z + v.w;
    ts[t] = s;
    __syncthreads();
#pragma unroll
    for (int off = 1; off < 256; off <<= 1) {
        int u = (t >= off) ? ts[t - off] : 0;
        __syncthreads();
        ts[t] += u;
        __syncthreads();
    }
    int ex = ts[t] - s;  // exclusive prefix of this thread

    if (base     < n) g_rowstart[base]     = ex;
    if (base + 1 < n) g_rowstart[base + 1] = ex + v.x;
    if (base + 2 < n) g_rowstart[base + 2] = ex + v.x + v.y;
    if (base + 3 < n) g_rowstart[base + 3] = ex + v.x + v.y + v.z;
    if (t == 255) g_bsums[blockIdx.x] = ts[255];
}

// Phase 2: scan block sums (single small block)
__global__ void k_scan_bsums(int nb, int n) {
    __shared__ int ts[128];
    const int t = threadIdx.x;
    int s = (t < nb) ? g_bsums[t] : 0;
    ts[t] = s;
    __syncthreads();
#pragma unroll
    for (int off = 1; off < 128; off <<= 1) {
        int u = (t >= off) ? ts[t - off] : 0;
        __syncthreads();
        ts[t] += u;
        __syncthreads();
    }
    if (t < nb) g_bsums[t] = ts[t] - s;  // exclusive
    if (t == 127) g_rowstart[n] = ts[127];  // total = E
}

// Phase 3: add block offsets, produce rowstart + cursor
__global__ void k_scan_add(int n) {
    int i = blockIdx.x * blockDim.x + threadIdx.x;
    if (i < n) {
        int v = g_rowstart[i] + g_bsums[i >> 10];
        g_rowstart[i] = v;
        g_cursor[i] = v;
    }
}

__global__ void k_fill(const int* __restrict__ row, const int* __restrict__ col, int e) {
    int i = blockIdx.x * blockDim.x + threadIdx.x;
    if (i < e) {
        int r = row[i];
        int pos = atomicAdd(&g_cursor[r], 1);
        g_colidx[pos] = col[i];
    }
}

// ---------------------------------------------------------------------------
// GEMM: hs[n,128] = dinv * (act(A)[n,128] @ W[128,128] + b)
// ---------------------------------------------------------------------------
template <bool RELU_IN>
__global__ void k_gemm(const float* __restrict__ A,
                       const float* __restrict__ W,
                       const float* __restrict__ b,
                       float* __restrict__ HSout,
                       int n) {
    __shared__ float As[64][64];    // 16KB
    __shared__ float Ws[64][128];   // 32KB

    const int t = threadIdx.x;
    const int row0 = blockIdx.x * 64;
    const int c = t & 31;
    const int r8 = (t >> 5) * 8;

    float acc[8][4];
#pragma unroll
    for (int i = 0; i < 8; i++)
#pragma unroll
        for (int j = 0; j < 4; j++) acc[i][j] = 0.0f;

    for (int kc = 0; kc < 2; kc++) {
        {
            const float4* Wv = (const float4*)W;
            float4* Wsv = (float4*)&Ws[0][0];
            int base = kc * 64 * 32;
#pragma unroll
            for (int j = 0; j < 8; j++) {
                int idx = t + j * 256;
                Wsv[idx] = Wv[base + idx];
            }
        }
        {
#pragma unroll
            for (int j = 0; j < 4; j++) {
                int idx = t + j * 256;
                int r = idx >> 4;
                int cc = idx & 15;
                int grow = row0 + r;
                float4 v = make_float4(0.f, 0.f, 0.f, 0.f);
                if (grow < n) v = ((const float4*)A)[(size_t)grow * 32 + kc * 16 + cc];
                if (RELU_IN) {
                    v.x = fmaxf(v.x, 0.f); v.y = fmaxf(v.y, 0.f);
                    v.z = fmaxf(v.z, 0.f); v.w = fmaxf(v.w, 0.f);
                }
                ((float4*)&As[r][0])[cc] = v;
            }
        }
        __syncthreads();

#pragma unroll 8
        for (int k = 0; k < 64; k++) {
            float4 w = ((const float4*)&Ws[k][0])[c];
#pragma unroll
            for (int i = 0; i < 8; i++) {
                float a = As[r8 + i][k];
                acc[i][0] = fmaf(a, w.x, acc[i][0]);
                acc[i][1] = fmaf(a, w.y, acc[i][1]);
                acc[i][2] = fmaf(a, w.z, acc[i][2]);
                acc[i][3] = fmaf(a, w.w, acc[i][3]);
            }
        }
        __syncthreads();
    }

    float4 bias = ((const float4*)b)[c];
#pragma unroll
    for (int i = 0; i < 8; i++) {
        int grow = row0 + r8 + i;
        if (grow < n) {
            float d = g_dinv[grow];
            float4 o;
            o.x = (acc[i][0] + bias.x) * d;
            o.y = (acc[i][1] + bias.y) * d;
            o.z = (acc[i][2] + bias.z) * d;
            o.w = (acc[i][3] + bias.w) * d;
            ((float4*)HSout)[(size_t)grow * 32 + c] = o;
        }
    }
}

// ---------------------------------------------------------------------------
// Gather: out[i] = dinv[i] * (hs[i] + sum_{j in N(i)} hs[j])
// One warp per row; each lane owns one float4 (4 of 128 features).
// ---------------------------------------------------------------------------
__global__ void k_gather(const float* __restrict__ hs,
                         float* __restrict__ out,
                         int n) {
    int warp = (blockIdx.x * blockDim.x + threadIdx.x) >> 5;
    int lane = threadIdx.x & 31;
    if (warp >= n) return;

    int s = g_rowstart[warp];
    int t_ = g_rowstart[warp + 1];

    float4 acc = ((const float4*)hs)[(size_t)warp * 32 + lane];  // self loop

    for (int e0 = s; e0 < t_; e0 += 32) {
        int j = 0;
        if (e0 + lane < t_) j = g_colidx[e0 + lane];
        int cnt = min(32, t_ - e0);
        for (int k = 0; k < cnt; k++) {
            int jj = __shfl_sync(0xffffffffu, j, k);
            float4 v = ((const float4*)hs)[(size_t)jj * 32 + lane];
            acc.x += v.x; acc.y += v.y; acc.z += v.z; acc.w += v.w;
        }
    }

    float d = g_dinv[warp];
    acc.x *= d; acc.y *= d; acc.z *= d; acc.w *= d;
    ((float4*)out)[(size_t)warp * 32 + lane] = acc;
}

// ---------------------------------------------------------------------------
// log_softmax in place, one warp per row
// ---------------------------------------------------------------------------
__global__ void k_log_softmax(float* __restrict__ out, int n) {
    int warp = (blockIdx.x * blockDim.x + threadIdx.x) >> 5;
    int lane = threadIdx.x & 31;
    if (warp >= n) return;
    float4 v = ((const float4*)out)[(size_t)warp * 32 + lane];
    float mx = fmaxf(fmaxf(v.x, v.y), fmaxf(v.z, v.w));
#pragma unroll
    for (int o = 16; o; o >>= 1) mx = fmaxf(mx, __shfl_xor_sync(0xffffffffu, mx, o));
    float s = expf(v.x - mx) + expf(v.y - mx) + expf(v.z - mx) + expf(v.w - mx);
#pragma unroll
    for (int o = 16; o; o >>= 1) s += __shfl_xor_sync(0xffffffffu, s, o);
    float lse = mx + logf(s);
    v.x -= lse; v.y -= lse; v.z -= lse; v.w -= lse;
    ((float4*)out)[(size_t)warp * 32 + lane] = v;
}

// ---------------------------------------------------------------------------
// Launch
// ---------------------------------------------------------------------------
extern "C" void kernel_launch(void* const* d_in, const int* in_sizes, int n_in,
                              void* d_out, int out_size) {
    const float* x  = (const float*)d_in[0];
    const float* W0 = (const float*)d_in[1];
    const float* b0 = (const float*)d_in[2];
    const float* W1 = (const float*)d_in[3];
    const float* b1 = (const float*)d_in[4];
    const int* row  = (const int*)d_in[5];
    const int* col  = (const int*)d_in[6];
    float* out = (float*)d_out;

    const int n = in_sizes[0] / FF;   // 100000
    const int e = in_sizes[5];        // 1600000

    float* hs;  cudaGetSymbolAddress((void**)&hs,  g_hs);
    float* agg; cudaGetSymbolAddress((void**)&agg, g_agg);

    const int nb = (n + 1023) / 1024;  // scan blocks

    // Degrees + CSR build (reused by both layers)
    k_zero_counts<<<(n + 4 + 255) / 256, 256>>>(n);
    k_hist<<<(e + 255) / 256, 256>>>(row, col, e);
    k_dinv<<<(n + 255) / 256, 256>>>(n);
    k_scan_partial<<<nb, 256>>>(n);
    k_scan_bsums<<<1, 128>>>(nb, n);
    k_scan_add<<<(n + 255) / 256, 256>>>(n);
    k_fill<<<(e + 255) / 256, 256>>>(row, col, e);

    const int gemm_blocks = (n + 63) / 64;
    const int gath_blocks = (n * 32 + 255) / 256;  // one warp per row

    // Layer 0
    k_gemm<false><<<gemm_blocks, 256>>>(x, W0, b0, hs, n);
    k_gather<<<gath_blocks, 256>>>(hs, agg, n);

    // Layer 1
    k_gemm<true><<<gemm_blocks, 256>>>(agg, W1, b1, hs, n);
    k_gather<<<gath_blocks, 256>>>(hs, out, n);

    k_log_softmax<<<(n * 32 + 255) / 256, 256>>>(out, n);
}

// round 4
// speedup vs baseline: 1.8316x; 1.1339x over previous
#include <cuda_runtime.h>
#include <cuda_fp16.h>
#include <cstdint>

#define NN 100000
#define FF 128
#define EE 1600000

// Scratch (static device arrays — no allocation APIs allowed)
__device__ __half g_hs[(size_t)NN * FF];   // fp16: dinv * (A@W + b)
__device__ float  g_agg[(size_t)NN * FF];  // layer-0 aggregation result (fp32)
__device__ float  g_dinv[NN];
__device__ int    g_rowcnt[NN + 4];        // +pad for int4 tail
__device__ int    g_colcnt[NN];
__device__ int    g_rowstart[NN + 1];
__device__ int    g_cursor[NN];
__device__ int    g_colidx[EE];
__device__ int    g_bsums[256];

// ---------------------------------------------------------------------------
// CSR build + degrees
// ---------------------------------------------------------------------------
__global__ void k_hist(const int* __restrict__ row, const int* __restrict__ col, int e) {
    int i = blockIdx.x * blockDim.x + threadIdx.x;
    if (i < e) {
        atomicAdd(&g_rowcnt[row[i]], 1);
        atomicAdd(&g_colcnt[col[i]], 1);
    }
}

__global__ void k_dinv(int n) {
    int i = blockIdx.x * blockDim.x + threadIdx.x;
    if (i < n) g_dinv[i] = rsqrtf((float)g_colcnt[i] + 1.0f);
}

// --- 3-phase exclusive scan of g_rowcnt -> g_rowstart ---
__global__ void k_scan_partial(int n) {
    __shared__ int ts[256];
    const int t = threadIdx.x;
    const int base = blockIdx.x * 1024 + t * 4;

    int4 v = make_int4(0, 0, 0, 0);
    if (base < n) v = *(const int4*)&g_rowcnt[base];

    int s = v.x + v.y + v.z + v.w;
    ts[t] = s;
    __syncthreads();
#pragma unroll
    for (int off = 1; off < 256; off <<= 1) {
        int u = (t >= off) ? ts[t - off] : 0;
        __syncthreads();
        ts[t] += u;
        __syncthreads();
    }
    int ex = ts[t] - s;

    if (base     < n) g_rowstart[base]     = ex;
    if (base + 1 < n) g_rowstart[base + 1] = ex + v.x;
    if (base + 2 < n) g_rowstart[base + 2] = ex + v.x + v.y;
    if (base + 3 < n) g_rowstart[base + 3] = ex + v.x + v.y + v.z;
    if (t == 255) g_bsums[blockIdx.x] = ts[255];
}

__global__ void k_scan_bsums(int nb, int n) {
    __shared__ int ts[128];
    const int t = threadIdx.x;
    int s = (t < nb) ? g_bsums[t] : 0;
    ts[t] = s;
    __syncthreads();
#pragma unroll
    for (int off = 1; off < 128; off <<= 1) {
        int u = (t >= off) ? ts[t - off] : 0;
        __syncthreads();
        ts[t] += u;
        __syncthreads();
    }
    if (t < nb) g_bsums[t] = ts[t] - s;
    if (t == 127) g_rowstart[n] = ts[127];
}

__global__ void k_scan_add(int n) {
    int i = blockIdx.x * blockDim.x + threadIdx.x;
    if (i < n) {
        int v = g_rowstart[i] + g_bsums[i >> 10];
        g_rowstart[i] = v;
        g_cursor[i] = v;
    }
}

__global__ void k_fill(const int* __restrict__ row, const int* __restrict__ col, int e) {
    int i = blockIdx.x * blockDim.x + threadIdx.x;
    if (i < e) {
        int r = row[i];
        int pos = atomicAdd(&g_cursor[r], 1);
        g_colidx[pos] = col[i];
    }
}

// ---------------------------------------------------------------------------
// GEMM: hs[n,128] (fp16) = dinv * (act(A)[n,128] @ W[128,128] + b)
// ---------------------------------------------------------------------------
template <bool RELU_IN>
__global__ void k_gemm(const float* __restrict__ A,
                       const float* __restrict__ W,
                       const float* __restrict__ b,
                       __half* __restrict__ HSout,
                       int n) {
    __shared__ float As[64][64];    // 16KB
    __shared__ float Ws[64][128];   // 32KB

    const int t = threadIdx.x;
    const int row0 = blockIdx.x * 64;
    const int c = t & 31;
    const int r8 = (t >> 5) * 8;

    float acc[8][4];
#pragma unroll
    for (int i = 0; i < 8; i++)
#pragma unroll
        for (int j = 0; j < 4; j++) acc[i][j] = 0.0f;

    for (int kc = 0; kc < 2; kc++) {
        {
            const float4* Wv = (const float4*)W;
            float4* Wsv = (float4*)&Ws[0][0];
            int base = kc * 64 * 32;
#pragma unroll
            for (int j = 0; j < 8; j++) {
                int idx = t + j * 256;
                Wsv[idx] = Wv[base + idx];
            }
        }
        {
#pragma unroll
            for (int j = 0; j < 4; j++) {
                int idx = t + j * 256;
                int r = idx >> 4;
                int cc = idx & 15;
                int grow = row0 + r;
                float4 v = make_float4(0.f, 0.f, 0.f, 0.f);
                if (grow < n) v = ((const float4*)A)[(size_t)grow * 32 + kc * 16 + cc];
                if (RELU_IN) {
                    v.x = fmaxf(v.x, 0.f); v.y = fmaxf(v.y, 0.f);
                    v.z = fmaxf(v.z, 0.f); v.w = fmaxf(v.w, 0.f);
                }
                ((float4*)&As[r][0])[cc] = v;
            }
        }
        __syncthreads();

#pragma unroll 8
        for (int k = 0; k < 64; k++) {
            float4 w = ((const float4*)&Ws[k][0])[c];
#pragma unroll
            for (int i = 0; i < 8; i++) {
                float a = As[r8 + i][k];
                acc[i][0] = fmaf(a, w.x, acc[i][0]);
                acc[i][1] = fmaf(a, w.y, acc[i][1]);
                acc[i][2] = fmaf(a, w.z, acc[i][2]);
                acc[i][3] = fmaf(a, w.w, acc[i][3]);
            }
        }
        __syncthreads();
    }

    float4 bias = ((const float4*)b)[c];
#pragma unroll
    for (int i = 0; i < 8; i++) {
        int grow = row0 + r8 + i;
        if (grow < n) {
            float d = g_dinv[grow];
            float ox = (acc[i][0] + bias.x) * d;
            float oy = (acc[i][1] + bias.y) * d;
            float oz = (acc[i][2] + bias.z) * d;
            float ow = (acc[i][3] + bias.w) * d;
            __half2 p0 = __floats2half2_rn(ox, oy);
            __half2 p1 = __floats2half2_rn(oz, ow);
            uint2 packed;
            packed.x = *(uint32_t*)&p0;
            packed.y = *(uint32_t*)&p1;
            ((uint2*)HSout)[(size_t)grow * 32 + c] = packed;
        }
    }
}

// ---------------------------------------------------------------------------
// Gather: out[i] = dinv[i] * (hs[i] + sum_{j in N(i)} hs[j])
// hs in fp16 (256B/row). One warp per row; each lane owns 4 features.
// If SOFTMAX, apply log_softmax to the row before writing.
// ---------------------------------------------------------------------------
template <bool SOFTMAX>
__global__ void k_gather(const __half* __restrict__ hs,
                         float* __restrict__ out,
                         int n) {
    int warp = (blockIdx.x * blockDim.x + threadIdx.x) >> 5;
    int lane = threadIdx.x & 31;
    if (warp >= n) return;

    int s = g_rowstart[warp];
    int t_ = g_rowstart[warp + 1];

    const uint2* hsv = (const uint2*)hs;

    // self loop
    float4 acc;
    {
        uint2 raw = hsv[(size_t)warp * 32 + lane];
        __half2 p0 = *(__half2*)&raw.x;
        __half2 p1 = *(__half2*)&raw.y;
        float2 f0 = __half22float2(p0);
        float2 f1 = __half22float2(p1);
        acc.x = f0.x; acc.y = f0.y; acc.z = f1.x; acc.w = f1.y;
    }

    for (int e0 = s; e0 < t_; e0 += 32) {
        int j = 0;
        if (e0 + lane < t_) j = g_colidx[e0 + lane];
        int cnt = min(32, t_ - e0);
        for (int k = 0; k < cnt; k++) {
            int jj = __shfl_sync(0xffffffffu, j, k);
            uint2 raw = hsv[(size_t)jj * 32 + lane];
            __half2 p0 = *(__half2*)&raw.x;
            __half2 p1 = *(__half2*)&raw.y;
            float2 f0 = __half22float2(p0);
            float2 f1 = __half22float2(p1);
            acc.x += f0.x; acc.y += f0.y; acc.z += f1.x; acc.w += f1.y;
        }
    }

    float d = g_dinv[warp];
    acc.x *= d; acc.y *= d; acc.z *= d; acc.w *= d;

    if (SOFTMAX) {
        float mx = fmaxf(fmaxf(acc.x, acc.y), fmaxf(acc.z, acc.w));
#pragma unroll
        for (int o = 16; o; o >>= 1) mx = fmaxf(mx, __shfl_xor_sync(0xffffffffu, mx, o));
        float sum = expf(acc.x - mx) + expf(acc.y - mx) + expf(acc.z - mx) + expf(acc.w - mx);
#pragma unroll
        for (int o = 16; o; o >>= 1) sum += __shfl_xor_sync(0xffffffffu, sum, o);
        float lse = mx + logf(sum);
        acc.x -= lse; acc.y -= lse; acc.z -= lse; acc.w -= lse;
    }

    ((float4*)out)[(size_t)warp * 32 + lane] = acc;
}

// ---------------------------------------------------------------------------
// Launch
// ---------------------------------------------------------------------------
extern "C" void kernel_launch(void* const* d_in, const int* in_sizes, int n_in,
                              void* d_out, int out_size) {
    const float* x  = (const float*)d_in[0];
    const float* W0 = (const float*)d_in[1];
    const float* b0 = (const float*)d_in[2];
    const float* W1 = (const float*)d_in[3];
    const float* b1 = (const float*)d_in[4];
    const int* row  = (const int*)d_in[5];
    const int* col  = (const int*)d_in[6];
    float* out = (float*)d_out;

    const int n = in_sizes[0] / FF;   // 100000
    const int e = in_sizes[5];        // 1600000

    __half* hs; cudaGetSymbolAddress((void**)&hs,  g_hs);
    float* agg; cudaGetSymbolAddress((void**)&agg, g_agg);
    int* rowcnt; cudaGetSymbolAddress((void**)&rowcnt, g_rowcnt);
    int* colcnt; cudaGetSymbolAddress((void**)&colcnt, g_colcnt);

    const int nb = (n + 1023) / 1024;

    // Degrees + CSR build (reused by both layers)
    cudaMemsetAsync(rowcnt, 0, (NN + 4) * sizeof(int), 0);
    cudaMemsetAsync(colcnt, 0, NN * sizeof(int), 0);
    k_hist<<<(e + 255) / 256, 256>>>(row, col, e);
    k_dinv<<<(n + 255) / 256, 256>>>(n);
    k_scan_partial<<<nb, 256>>>(n);
    k_scan_bsums<<<1, 128>>>(nb, n);
    k_scan_add<<<(n + 255) / 256, 256>>>(n);
    k_fill<<<(e + 255) / 256, 256>>>(row, col, e);

    const int gemm_blocks = (n + 63) / 64;
    const int gath_blocks = (n * 32 + 255) / 256;

    // Layer 0
    k_gemm<false><<<gemm_blocks, 256>>>(x, W0, b0, hs, n);
    k_gather<false><<<gath_blocks, 256>>>(hs, agg, n);

    // Layer 1 (gather fused with log_softmax)
    k_gemm<true><<<gemm_blocks, 256>>>(agg, W1, b1, hs, n);
    k_gather<true><<<gath_blocks, 256>>>(hs, out, n);
}

// round 5
// speedup vs baseline: 2.7420x; 1.4970x over previous
#include <cuda_runtime.h>
#include <cuda_fp16.h>
#include <mma.h>
#include <cstdint>

using namespace nvcuda;

#define NN 100000
#define FF 128
#define EE 1600000

// Scratch (static device arrays — no allocation APIs allowed)
__device__ __half g_hs[(size_t)NN * FF];    // fp16: dinv * (A@W + b)
__device__ __half g_aggh[(size_t)NN * FF];  // fp16: relu(layer-0 aggregation)
__device__ __half g_w0h[FF * FF];
__device__ __half g_w1h[FF * FF];
__device__ float  g_dinv[NN];
__device__ int    g_rowcnt[NN + 4];
__device__ int    g_colcnt[NN];
__device__ int    g_rowstart[NN + 1];
__device__ int    g_cursor[NN];
__device__ int    g_colidx[EE];
__device__ int    g_bsums[256];

// ---------------------------------------------------------------------------
// Weight conversion fp32 -> fp16 (once per launch, tiny)
// ---------------------------------------------------------------------------
__global__ void k_convW(const float* __restrict__ W, __half* __restrict__ Wh) {
    int i = blockIdx.x * blockDim.x + threadIdx.x;  // 0..4095, one float4 each
    float4 v = ((const float4*)W)[i];
    __half2 h0 = __floats2half2_rn(v.x, v.y);
    __half2 h1 = __floats2half2_rn(v.z, v.w);
    uint2 p; p.x = *(uint32_t*)&h0; p.y = *(uint32_t*)&h1;
    ((uint2*)Wh)[i] = p;
}

// ---------------------------------------------------------------------------
// CSR build + degrees
// ---------------------------------------------------------------------------
__global__ void k_hist(const int* __restrict__ row, const int* __restrict__ col, int e) {
    int i = blockIdx.x * blockDim.x + threadIdx.x;
    if (i < e) {
        atomicAdd(&g_rowcnt[row[i]], 1);
        atomicAdd(&g_colcnt[col[i]], 1);
    }
}

__global__ void k_dinv(int n) {
    int i = blockIdx.x * blockDim.x + threadIdx.x;
    if (i < n) g_dinv[i] = rsqrtf((float)g_colcnt[i] + 1.0f);
}

__global__ void k_scan_partial(int n) {
    __shared__ int ts[256];
    const int t = threadIdx.x;
    const int base = blockIdx.x * 1024 + t * 4;

    int4 v = make_int4(0, 0, 0, 0);
    if (base < n) v = *(const int4*)&g_rowcnt[base];

    int s = v.x + v.y + v.z + v.w;
    ts[t] = s;
    __syncthreads();
#pragma unroll
    for (int off = 1; off < 256; off <<= 1) {
        int u = (t >= off) ? ts[t - off] : 0;
        __syncthreads();
        ts[t] += u;
        __syncthreads();
    }
    int ex = ts[t] - s;

    if (base     < n) g_rowstart[base]     = ex;
    if (base + 1 < n) g_rowstart[base + 1] = ex + v.x;
    if (base + 2 < n) g_rowstart[base + 2] = ex + v.x + v.y;
    if (base + 3 < n) g_rowstart[base + 3] = ex + v.x + v.y + v.z;
    if (t == 255) g_bsums[blockIdx.x] = ts[255];
}

__global__ void k_scan_bsums(int nb, int n) {
    __shared__ int ts[128];
    const int t = threadIdx.x;
    int s = (t < nb) ? g_bsums[t] : 0;
    ts[t] = s;
    __syncthreads();
#pragma unroll
    for (int off = 1; off < 128; off <<= 1) {
        int u = (t >= off) ? ts[t - off] : 0;
        __syncthreads();
        ts[t] += u;
        __syncthreads();
    }
    if (t < nb) g_bsums[t] = ts[t] - s;
    if (t == 127) g_rowstart[n] = ts[127];
}

__global__ void k_scan_add(int n) {
    int i = blockIdx.x * blockDim.x + threadIdx.x;
    if (i < n) {
        int v = g_rowstart[i] + g_bsums[i >> 10];
        g_rowstart[i] = v;
        g_cursor[i] = v;
    }
}

__global__ void k_fill(const int* __restrict__ row, const int* __restrict__ col, int e) {
    int i = blockIdx.x * blockDim.x + threadIdx.x;
    if (i < e) {
        int r = row[i];
        int pos = atomicAdd(&g_cursor[r], 1);
        g_colidx[pos] = col[i];
    }
}

// ---------------------------------------------------------------------------
// Tensor-core GEMM: hs[n,128] (fp16) = dinv * (A[n,128] @ W[128,128] + b)
// A is fp32 (layer 0) or fp16 (layer 1, already relu'd by gather-0).
// Block = 64 rows x 128 cols, 8 warps (4 row-groups x 2 col-groups).
// ---------------------------------------------------------------------------
#define AS_STRIDE 136   // halves (272B, 16B-multiple)
#define CS_STRIDE 132   // floats (528B, 16B-multiple)

template <bool A_FP32>
__launch_bounds__(256, 4)
__global__ void k_gemm(const void* __restrict__ Ain,
                       const __half* __restrict__ Wh,
                       const float* __restrict__ b,
                       __half* __restrict__ HSout,
                       int n) {
    __shared__ __align__(256) char smem_buf[2 * 64 * AS_STRIDE * 2];  // 34816B
    __half* As = (__half*)smem_buf;                      // 64 x AS_STRIDE
    __half* Ws = As + 64 * AS_STRIDE;                    // 64 x AS_STRIDE (W k-chunk)
    float* Cs = (float*)smem_buf;                        // 64 x CS_STRIDE (epilogue)

    const int t = threadIdx.x;
    const int row0 = blockIdx.x * 64;
    const int w = t >> 5;
    const int wr = w >> 1;   // 0..3 : rows [wr*16, wr*16+16)
    const int wc = w & 1;    // 0..1 : cols [wc*64, wc*64+64)

    wmma::fragment<wmma::accumulator, 16, 16, 16, float> acc[4];
#pragma unroll
    for (int j = 0; j < 4; j++) wmma::fill_fragment(acc[j], 0.0f);

    for (int kc = 0; kc < 2; kc++) {
        // Load W chunk: rows [kc*64, kc*64+64), 128 halves/row = 16 uint4/row
        {
            const uint4* Wv = (const uint4*)Wh;
#pragma unroll
            for (int j = 0; j < 4; j++) {
                int idx = t + j * 256;          // 0..1023
                int r = idx >> 4;
                int c = idx & 15;
                *(uint4*)&Ws[r * AS_STRIDE + c * 8] = Wv[(kc * 64 + r) * 16 + c];
            }
        }
        // Load A tile: 64 rows x 64-col chunk, convert to fp16 if needed
        if (A_FP32) {
            const float4* Av = (const float4*)Ain;
#pragma unroll
            for (int j = 0; j < 4; j++) {
                int idx = t + j * 256;          // 0..1023
                int r = idx >> 4;               // 64 rows
                int cc = idx & 15;              // 16 float4 per 64-col chunk
                int grow = row0 + r;
                float4 v = make_float4(0.f, 0.f, 0.f, 0.f);
                if (grow < n) v = Av[(size_t)grow * 32 + kc * 16 + cc];
                __half2 h0 = __floats2half2_rn(v.x, v.y);
                __half2 h1 = __floats2half2_rn(v.z, v.w);
                uint2 p; p.x = *(uint32_t*)&h0; p.y = *(uint32_t*)&h1;
                *(uint2*)&As[r * AS_STRIDE + cc * 4] = p;
            }
        } else {
            const uint4* Av = (const uint4*)Ain;
#pragma unroll
            for (int j = 0; j < 2; j++) {
                int idx = t + j * 256;          // 0..511
                int r = idx >> 3;               // 64 rows
                int cc = idx & 7;               // 8 uint4 per 64-col chunk
                int grow = row0 + r;
                uint4 v = make_uint4(0u, 0u, 0u, 0u);
                if (grow < n) v = Av[(size_t)grow * 16 + kc * 8 + cc];
                *(uint4*)&As[r * AS_STRIDE + cc * 8] = v;
            }
        }
        __syncthreads();

#pragma unroll
        for (int k = 0; k < 4; k++) {
            wmma::fragment<wmma::matrix_a, 16, 16, 16, __half, wmma::row_major> af;
            wmma::load_matrix_sync(af, As + (wr * 16) * AS_STRIDE + k * 16, AS_STRIDE);
#pragma unroll
            for (int j = 0; j < 4; j++) {
                wmma::fragment<wmma::matrix_b, 16, 16, 16, __half, wmma::row_major> bf;
                wmma::load_matrix_sync(bf, Ws + (k * 16) * AS_STRIDE + wc * 64 + j * 16, AS_STRIDE);
                wmma::mma_sync(acc[j], af, bf, acc[j]);
            }
        }
        __syncthreads();
    }

    // Epilogue: acc -> smem (fp32), then bias + dinv scale + fp16 pack
#pragma unroll
    for (int j = 0; j < 4; j++)
        wmma::store_matrix_sync(Cs + (wr * 16) * CS_STRIDE + wc * 64 + j * 16,
                                acc[j], CS_STRIDE, wmma::mem_row_major);
    __syncthreads();

#pragma unroll
    for (int j = 0; j < 4; j++) {
        int idx = t + j * 256;       // 0..1023 : 64 rows x 16 groups of 8 cols
        int r = idx >> 4;
        int c = idx & 15;
        int grow = row0 + r;
        if (grow < n) {
            float4 f0 = *(float4*)&Cs[r * CS_STRIDE + c * 8];
            float4 f1 = *(float4*)&Cs[r * CS_STRIDE + c * 8 + 4];
            float4 b0 = ((const float4*)b)[c * 2];
            float4 b1 = ((const float4*)b)[c * 2 + 1];
            float d = g_dinv[grow];
            __half2 h0 = __floats2half2_rn((f0.x + b0.x) * d, (f0.y + b0.y) * d);
            __half2 h1 = __floats2half2_rn((f0.z + b0.z) * d, (f0.w + b0.w) * d);
            __half2 h2 = __floats2half2_rn((f1.x + b1.x) * d, (f1.y + b1.y) * d);
            __half2 h3 = __floats2half2_rn((f1.z + b1.z) * d, (f1.w + b1.w) * d);
            uint4 p;
            p.x = *(uint32_t*)&h0; p.y = *(uint32_t*)&h1;
            p.z = *(uint32_t*)&h2; p.w = *(uint32_t*)&h3;
            ((uint4*)HSout)[(size_t)grow * 16 + c] = p;
        }
    }
}

// ---------------------------------------------------------------------------
// Gather: res[i] = dinv[i] * (hs[i] + sum_{j in N(i)} hs[j])
// MODE 0: out = fp16, relu applied (layer-0 -> GEMM-1 input)
// MODE 1: out = fp32, log_softmax applied (final output)
// ---------------------------------------------------------------------------
template <int MODE>
__global__ void k_gather(const __half* __restrict__ hs,
                         void* __restrict__ out,
                         int n) {
    int warp = (blockIdx.x * blockDim.x + threadIdx.x) >> 5;
    int lane = threadIdx.x & 31;
    if (warp >= n) return;

    int s = g_rowstart[warp];
    int t_ = g_rowstart[warp + 1];

    const uint2* hsv = (const uint2*)hs;

    float4 acc;
    {
        uint2 raw = hsv[(size_t)warp * 32 + lane];
        float2 f0 = __half22float2(*(__half2*)&raw.x);
        float2 f1 = __half22float2(*(__half2*)&raw.y);
        acc.x = f0.x; acc.y = f0.y; acc.z = f1.x; acc.w = f1.y;
    }

    for (int e0 = s; e0 < t_; e0 += 32) {
        int j = 0;
        if (e0 + lane < t_) j = g_colidx[e0 + lane];
        int cnt = min(32, t_ - e0);
        for (int k = 0; k < cnt; k++) {
            int jj = __shfl_sync(0xffffffffu, j, k);
            uint2 raw = hsv[(size_t)jj * 32 + lane];
            float2 f0 = __half22float2(*(__half2*)&raw.x);
            float2 f1 = __half22float2(*(__half2*)&raw.y);
            acc.x += f0.x; acc.y += f0.y; acc.z += f1.x; acc.w += f1.y;
        }
    }

    float d = g_dinv[warp];
    acc.x *= d; acc.y *= d; acc.z *= d; acc.w *= d;

    if (MODE == 0) {
        // relu + fp16
        acc.x = fmaxf(acc.x, 0.f); acc.y = fmaxf(acc.y, 0.f);
        acc.z = fmaxf(acc.z, 0.f); acc.w = fmaxf(acc.w, 0.f);
        __half2 h0 = __floats2half2_rn(acc.x, acc.y);
        __half2 h1 = __floats2half2_rn(acc.z, acc.w);
        uint2 p; p.x = *(uint32_t*)&h0; p.y = *(uint32_t*)&h1;
        ((uint2*)out)[(size_t)warp * 32 + lane] = p;
    } else {
        float mx = fmaxf(fmaxf(acc.x, acc.y), fmaxf(acc.z, acc.w));
#pragma unroll
        for (int o = 16; o; o >>= 1) mx = fmaxf(mx, __shfl_xor_sync(0xffffffffu, mx, o));
        float sum = expf(acc.x - mx) + expf(acc.y - mx) + expf(acc.z - mx) + expf(acc.w - mx);
#pragma unroll
        for (int o = 16; o; o >>= 1) sum += __shfl_xor_sync(0xffffffffu, sum, o);
        float lse = mx + logf(sum);
        acc.x -= lse; acc.y -= lse; acc.z -= lse; acc.w -= lse;
        ((float4*)out)[(size_t)warp * 32 + lane] = acc;
    }
}

// ---------------------------------------------------------------------------
// Launch
// ---------------------------------------------------------------------------
extern "C" void kernel_launch(void* const* d_in, const int* in_sizes, int n_in,
                              void* d_out, int out_size) {
    const float* x  = (const float*)d_in[0];
    const float* W0 = (const float*)d_in[1];
    const float* b0 = (const float*)d_in[2];
    const float* W1 = (const float*)d_in[3];
    const float* b1 = (const float*)d_in[4];
    const int* row  = (const int*)d_in[5];
    const int* col  = (const int*)d_in[6];
    float* out = (float*)d_out;

    const int n = in_sizes[0] / FF;   // 100000
    const int e = in_sizes[5];        // 1600000

    __half* hs;   cudaGetSymbolAddress((void**)&hs,   g_hs);
    __half* aggh; cudaGetSymbolAddress((void**)&aggh, g_aggh);
    __half* w0h;  cudaGetSymbolAddress((void**)&w0h,  g_w0h);
    __half* w1h;  cudaGetSymbolAddress((void**)&w1h,  g_w1h);
    int* rowcnt;  cudaGetSymbolAddress((void**)&rowcnt, g_rowcnt);
    int* colcnt;  cudaGetSymbolAddress((void**)&colcnt, g_colcnt);

    const int nb = (n + 1023) / 1024;

    // Weight conversion + degrees + CSR build
    k_convW<<<16, 256>>>(W0, w0h);
    k_convW<<<16, 256>>>(W1, w1h);
    cudaMemsetAsync(rowcnt, 0, (NN + 4) * sizeof(int), 0);
    cudaMemsetAsync(colcnt, 0, NN * sizeof(int), 0);
    k_hist<<<(e + 255) / 256, 256>>>(row, col, e);
    k_dinv<<<(n + 255) / 256, 256>>>(n);
    k_scan_partial<<<nb, 256>>>(n);
    k_scan_bsums<<<1, 128>>>(nb, n);
    k_scan_add<<<(n + 255) / 256, 256>>>(n);
    k_fill<<<(e + 255) / 256, 256>>>(row, col, e);

    const int gemm_blocks = (n + 63) / 64;
    const int gath_blocks = (n * 32 + 255) / 256;

    // Layer 0
    k_gemm<true><<<gemm_blocks, 256>>>(x, w0h, b0, hs, n);
    k_gather<0><<<gath_blocks, 256>>>(hs, aggh, n);

    // Layer 1
    k_gemm<false><<<gemm_blocks, 256>>>(aggh, w1h, b1, hs, n);
    k_gather<1><<<gath_blocks, 256>>>(hs, out, n);
}

// round 6
// speedup vs baseline: 2.8273x; 1.0311x over previous
#include <cuda_runtime.h>
#include <cuda_fp16.h>
#include <mma.h>
#include <cstdint>

using namespace nvcuda;

#define NN 100000
#define FF 128
#define EE 1600000

// Scratch (static device arrays — no allocation APIs allowed)
__device__ __half g_hs[(size_t)NN * FF];    // fp16 GEMM output
__device__ __half g_aggh[(size_t)NN * FF];  // fp16: relu(layer-0 aggregation)
__device__ __half g_w0h[FF * FF];
__device__ __half g_w1h[FF * FF];
__device__ float  g_dinv[NN];
__device__ int    g_rowcnt[NN + 4];
__device__ int    g_colcnt[NN];
__device__ int    g_rowstart[NN + 1];
__device__ int    g_cursor[NN];
__device__ int    g_colidx[EE];
__device__ int    g_bsums[256];

// ---------------------------------------------------------------------------
// Weight conversion fp32 -> fp16 (both weights, one kernel)
// ---------------------------------------------------------------------------
__global__ void k_convW(const float* __restrict__ W0, const float* __restrict__ W1) {
    int i = blockIdx.x * blockDim.x + threadIdx.x;  // 0..8191
    const float* W = (i < 4096) ? W0 : W1;
    __half* Wh = (i < 4096) ? g_w0h : g_w1h;
    int k = i & 4095;
    float4 v = ((const float4*)W)[k];
    __half2 h0 = __floats2half2_rn(v.x, v.y);
    __half2 h1 = __floats2half2_rn(v.z, v.w);
    uint2 p; p.x = *(uint32_t*)&h0; p.y = *(uint32_t*)&h1;
    ((uint2*)Wh)[k] = p;
}

// ---------------------------------------------------------------------------
// CSR build + degrees
// ---------------------------------------------------------------------------
__global__ void k_hist(const int* __restrict__ row, const int* __restrict__ col, int e) {
    int i = blockIdx.x * blockDim.x + threadIdx.x;
    int base = i * 4;
    if (base + 3 < e) {
        int4 r = *(const int4*)&row[base];
        int4 c = *(const int4*)&col[base];
        atomicAdd(&g_rowcnt[r.x], 1); atomicAdd(&g_rowcnt[r.y], 1);
        atomicAdd(&g_rowcnt[r.z], 1); atomicAdd(&g_rowcnt[r.w], 1);
        atomicAdd(&g_colcnt[c.x], 1); atomicAdd(&g_colcnt[c.y], 1);
        atomicAdd(&g_colcnt[c.z], 1); atomicAdd(&g_colcnt[c.w], 1);
    } else {
        for (int k = base; k < e; k++) {
            atomicAdd(&g_rowcnt[row[k]], 1);
            atomicAdd(&g_colcnt[col[k]], 1);
        }
    }
}

__global__ void k_scan_partial(int n) {
    __shared__ int ts[256];
    const int t = threadIdx.x;
    const int base = blockIdx.x * 1024 + t * 4;

    int4 v = make_int4(0, 0, 0, 0);
    if (base < n) v = *(const int4*)&g_rowcnt[base];

    int s = v.x + v.y + v.z + v.w;
    ts[t] = s;
    __syncthreads();
#pragma unroll
    for (int off = 1; off < 256; off <<= 1) {
        int u = (t >= off) ? ts[t - off] : 0;
        __syncthreads();
        ts[t] += u;
        __syncthreads();
    }
    int ex = ts[t] - s;

    if (base     < n) g_rowstart[base]     = ex;
    if (base + 1 < n) g_rowstart[base + 1] = ex + v.x;
    if (base + 2 < n) g_rowstart[base + 2] = ex + v.x + v.y;
    if (base + 3 < n) g_rowstart[base + 3] = ex + v.x + v.y + v.z;
    if (t == 255) g_bsums[blockIdx.x] = ts[255];
}

__global__ void k_scan_bsums(int nb, int n) {
    __shared__ int ts[128];
    const int t = threadIdx.x;
    int s = (t < nb) ? g_bsums[t] : 0;
    ts[t] = s;
    __syncthreads();
#pragma unroll
    for (int off = 1; off < 128; off <<= 1) {
        int u = (t >= off) ? ts[t - off] : 0;
        __syncthreads();
        ts[t] += u;
        __syncthreads();
    }
    if (t < nb) g_bsums[t] = ts[t] - s;
    if (t == 127) g_rowstart[n] = ts[127];
}

// Adds block offsets AND computes dinv (fused)
__global__ void k_scan_add_dinv(int n) {
    int i = blockIdx.x * blockDim.x + threadIdx.x;
    if (i < n) {
        int v = g_rowstart[i] + g_bsums[i >> 10];
        g_rowstart[i] = v;
        g_cursor[i] = v;
        g_dinv[i] = rsqrtf((float)g_colcnt[i] + 1.0f);
    }
}

__global__ void k_fill(const int* __restrict__ row, const int* __restrict__ col, int e) {
    int i = blockIdx.x * blockDim.x + threadIdx.x;
    if (i < e) {
        int r = row[i];
        int pos = atomicAdd(&g_cursor[r], 1);
        g_colidx[pos] = col[i];
    }
}

// ---------------------------------------------------------------------------
// Tensor-core GEMM: hs[n,128] (fp16) = [dinv *] (A[n,128] @ W[128,128] + b)
// ---------------------------------------------------------------------------
#define AS_STRIDE 136   // halves
#define CS_STRIDE 132   // floats

template <bool A_FP32, bool EPI_DINV>
__launch_bounds__(256, 4)
__global__ void k_gemm(const void* __restrict__ Ain,
                       const __half* __restrict__ Wh,
                       const float* __restrict__ b,
                       __half* __restrict__ HSout,
                       int n) {
    __shared__ __align__(256) char smem_buf[2 * 64 * AS_STRIDE * 2];
    __half* As = (__half*)smem_buf;
    __half* Ws = As + 64 * AS_STRIDE;
    float* Cs = (float*)smem_buf;

    const int t = threadIdx.x;
    const int row0 = blockIdx.x * 64;
    const int w = t >> 5;
    const int wr = w >> 1;
    const int wc = w & 1;

    wmma::fragment<wmma::accumulator, 16, 16, 16, float> acc[4];
#pragma unroll
    for (int j = 0; j < 4; j++) wmma::fill_fragment(acc[j], 0.0f);

    for (int kc = 0; kc < 2; kc++) {
        {
            const uint4* Wv = (const uint4*)Wh;
#pragma unroll
            for (int j = 0; j < 4; j++) {
                int idx = t + j * 256;
                int r = idx >> 4;
                int c = idx & 15;
                *(uint4*)&Ws[r * AS_STRIDE + c * 8] = Wv[(kc * 64 + r) * 16 + c];
            }
        }
        if (A_FP32) {
            const float4* Av = (const float4*)Ain;
#pragma unroll
            for (int j = 0; j < 4; j++) {
                int idx = t + j * 256;
                int r = idx >> 4;
                int cc = idx & 15;
                int grow = row0 + r;
                float4 v = make_float4(0.f, 0.f, 0.f, 0.f);
                if (grow < n) v = Av[(size_t)grow * 32 + kc * 16 + cc];
                __half2 h0 = __floats2half2_rn(v.x, v.y);
                __half2 h1 = __floats2half2_rn(v.z, v.w);
                uint2 p; p.x = *(uint32_t*)&h0; p.y = *(uint32_t*)&h1;
                *(uint2*)&As[r * AS_STRIDE + cc * 4] = p;
            }
        } else {
            const uint4* Av = (const uint4*)Ain;
#pragma unroll
            for (int j = 0; j < 2; j++) {
                int idx = t + j * 256;
                int r = idx >> 3;
                int cc = idx & 7;
                int grow = row0 + r;
                uint4 v = make_uint4(0u, 0u, 0u, 0u);
                if (grow < n) v = Av[(size_t)grow * 16 + kc * 8 + cc];
                *(uint4*)&As[r * AS_STRIDE + cc * 8] = v;
            }
        }
        __syncthreads();

#pragma unroll
        for (int k = 0; k < 4; k++) {
            wmma::fragment<wmma::matrix_a, 16, 16, 16, __half, wmma::row_major> af;
            wmma::load_matrix_sync(af, As + (wr * 16) * AS_STRIDE + k * 16, AS_STRIDE);
#pragma unroll
            for (int j = 0; j < 4; j++) {
                wmma::fragment<wmma::matrix_b, 16, 16, 16, __half, wmma::row_major> bf;
                wmma::load_matrix_sync(bf, Ws + (k * 16) * AS_STRIDE + wc * 64 + j * 16, AS_STRIDE);
                wmma::mma_sync(acc[j], af, bf, acc[j]);
            }
        }
        __syncthreads();
    }

#pragma unroll
    for (int j = 0; j < 4; j++)
        wmma::store_matrix_sync(Cs + (wr * 16) * CS_STRIDE + wc * 64 + j * 16,
                                acc[j], CS_STRIDE, wmma::mem_row_major);
    __syncthreads();

#pragma unroll
    for (int j = 0; j < 4; j++) {
        int idx = t + j * 256;
        int r = idx >> 4;
        int c = idx & 15;
        int grow = row0 + r;
        if (grow < n) {
            float4 f0 = *(float4*)&Cs[r * CS_STRIDE + c * 8];
            float4 f1 = *(float4*)&Cs[r * CS_STRIDE + c * 8 + 4];
            float4 b0 = ((const float4*)b)[c * 2];
            float4 b1 = ((const float4*)b)[c * 2 + 1];
            float d = EPI_DINV ? g_dinv[grow] : 1.0f;
            __half2 h0 = __floats2half2_rn((f0.x + b0.x) * d, (f0.y + b0.y) * d);
            __half2 h1 = __floats2half2_rn((f0.z + b0.z) * d, (f0.w + b0.w) * d);
            __half2 h2 = __floats2half2_rn((f1.x + b1.x) * d, (f1.y + b1.y) * d);
            __half2 h3 = __floats2half2_rn((f1.z + b1.z) * d, (f1.w + b1.w) * d);
            uint4 p;
            p.x = *(uint32_t*)&h0; p.y = *(uint32_t*)&h1;
            p.z = *(uint32_t*)&h2; p.w = *(uint32_t*)&h3;
            ((uint4*)HSout)[(size_t)grow * 16 + c] = p;
        }
    }
}

// ---------------------------------------------------------------------------
// Gather. MODE 0: hs has NO dinv folded -> per-neighbor dinv[j] weight,
//                 self term weighted dinv[i]; relu; fp16 out.
// MODE 1: hs has dinv folded -> plain sum; log_softmax; fp32 out.
// Inner loop unrolled x4 for MLP.
// ---------------------------------------------------------------------------
template <int MODE>
__global__ void k_gather(const __half* __restrict__ hs,
                         void* __restrict__ out,
                         int n) {
    int warp = (blockIdx.x * blockDim.x + threadIdx.x) >> 5;
    int lane = threadIdx.x & 31;
    if (warp >= n) return;

    int s = g_rowstart[warp];
    int t_ = g_rowstart[warp + 1];
    float di = g_dinv[warp];

    const uint2* hsv = (const uint2*)hs;

    float4 acc;
    {
        uint2 raw = hsv[(size_t)warp * 32 + lane];
        float2 f0 = __half22float2(*(__half2*)&raw.x);
        float2 f1 = __half22float2(*(__half2*)&raw.y);
        float sw = (MODE == 0) ? di : 1.0f;   // self weight
        acc.x = f0.x * sw; acc.y = f0.y * sw; acc.z = f1.x * sw; acc.w = f1.y * sw;
    }

    for (int e0 = s; e0 < t_; e0 += 32) {
        int idx = e0 + lane;
        int j = 0;
        float dj = 1.0f;
        if (idx < t_) {
            j = g_colidx[idx];
            if (MODE == 0) dj = g_dinv[j];
        }
        int cnt = min(32, t_ - e0);
        int k = 0;
        for (; k + 4 <= cnt; k += 4) {
            int j0 = __shfl_sync(0xffffffffu, j, k);
            int j1 = __shfl_sync(0xffffffffu, j, k + 1);
            int j2 = __shfl_sync(0xffffffffu, j, k + 2);
            int j3 = __shfl_sync(0xffffffffu, j, k + 3);
            float d0 = 1.f, d1 = 1.f, d2 = 1.f, d3 = 1.f;
            if (MODE == 0) {
                d0 = __shfl_sync(0xffffffffu, dj, k);
                d1 = __shfl_sync(0xffffffffu, dj, k + 1);
                d2 = __shfl_sync(0xffffffffu, dj, k + 2);
                d3 = __shfl_sync(0xffffffffu, dj, k + 3);
            }
            uint2 r0 = hsv[(size_t)j0 * 32 + lane];
            uint2 r1 = hsv[(size_t)j1 * 32 + lane];
            uint2 r2 = hsv[(size_t)j2 * 32 + lane];
            uint2 r3 = hsv[(size_t)j3 * 32 + lane];
#define ACC_ADD(raw, dd) { \
            float2 a0 = __half22float2(*(__half2*)&(raw).x); \
            float2 a1 = __half22float2(*(__half2*)&(raw).y); \
            acc.x = fmaf(a0.x, (dd), acc.x); acc.y = fmaf(a0.y, (dd), acc.y); \
            acc.z = fmaf(a1.x, (dd), acc.z); acc.w = fmaf(a1.y, (dd), acc.w); }
            ACC_ADD(r0, d0) ACC_ADD(r1, d1) ACC_ADD(r2, d2) ACC_ADD(r3, d3)
        }
        for (; k < cnt; k++) {
            int jj = __shfl_sync(0xffffffffu, j, k);
            float dd = (MODE == 0) ? __shfl_sync(0xffffffffu, dj, k) : 1.0f;
            uint2 raw = hsv[(size_t)jj * 32 + lane];
            ACC_ADD(raw, dd)
        }
#undef ACC_ADD
    }

    acc.x *= di; acc.y *= di; acc.z *= di; acc.w *= di;

    if (MODE == 0) {
        acc.x = fmaxf(acc.x, 0.f); acc.y = fmaxf(acc.y, 0.f);
        acc.z = fmaxf(acc.z, 0.f); acc.w = fmaxf(acc.w, 0.f);
        __half2 h0 = __floats2half2_rn(acc.x, acc.y);
        __half2 h1 = __floats2half2_rn(acc.z, acc.w);
        uint2 p; p.x = *(uint32_t*)&h0; p.y = *(uint32_t*)&h1;
        ((uint2*)out)[(size_t)warp * 32 + lane] = p;
    } else {
        float mx = fmaxf(fmaxf(acc.x, acc.y), fmaxf(acc.z, acc.w));
#pragma unroll
        for (int o = 16; o; o >>= 1) mx = fmaxf(mx, __shfl_xor_sync(0xffffffffu, mx, o));
        float sum = expf(acc.x - mx) + expf(acc.y - mx) + expf(acc.z - mx) + expf(acc.w - mx);
#pragma unroll
        for (int o = 16; o; o >>= 1) sum += __shfl_xor_sync(0xffffffffu, sum, o);
        float lse = mx + logf(sum);
        acc.x -= lse; acc.y -= lse; acc.z -= lse; acc.w -= lse;
        ((float4*)out)[(size_t)warp * 32 + lane] = acc;
    }
}

// ---------------------------------------------------------------------------
// Launch — fork-join capture: branch A (convW + GEMM0) || branch B (CSR build)
// ---------------------------------------------------------------------------
extern "C" void kernel_launch(void* const* d_in, const int* in_sizes, int n_in,
                              void* d_out, int out_size) {
    const float* x  = (const float*)d_in[0];
    const float* W0 = (const float*)d_in[1];
    const float* b0 = (const float*)d_in[2];
    const float* W1 = (const float*)d_in[3];
    const float* b1 = (const float*)d_in[4];
    const int* row  = (const int*)d_in[5];
    const int* col  = (const int*)d_in[6];
    float* out = (float*)d_out;

    const int n = in_sizes[0] / FF;   // 100000
    const int e = in_sizes[5];        // 1600000

    __half* hs;   cudaGetSymbolAddress((void**)&hs,   g_hs);
    __half* aggh; cudaGetSymbolAddress((void**)&aggh, g_aggh);
    __half* w0h;  cudaGetSymbolAddress((void**)&w0h,  g_w0h);
    __half* w1h;  cudaGetSymbolAddress((void**)&w1h,  g_w1h);
    int* rowcnt;  cudaGetSymbolAddress((void**)&rowcnt, g_rowcnt);
    int* colcnt;  cudaGetSymbolAddress((void**)&colcnt, g_colcnt);

    const int nb = (n + 1023) / 1024;
    const int gemm_blocks = (n + 63) / 64;
    const int gath_blocks = (n * 32 + 255) / 256;

    // Fork a side stream for the independent GEMM-0 chain.
    // (Created per call and intentionally not destroyed: destroying a stream
    // that participated in an active capture invalidates the capture, and
    // kernel_launch is only invoked a handful of times.)
    cudaStream_t sA;
    cudaStreamCreate(&sA);
    cudaEvent_t evFork, evJoin;
    cudaEventCreateWithFlags(&evFork, cudaEventDisableTiming);
    cudaEventCreateWithFlags(&evJoin, cudaEventDisableTiming);

    cudaEventRecord(evFork, 0);
    cudaStreamWaitEvent(sA, evFork, 0);

    // Branch A: weights -> fp16, GEMM0 (no dinv in epilogue)
    k_convW<<<32, 256, 0, sA>>>(W0, W1);
    k_gemm<true, false><<<gemm_blocks, 256, 0, sA>>>(x, w0h, b0, hs, n);
    cudaEventRecord(evJoin, sA);

    // Branch B (main stream): CSR build + dinv
    cudaMemsetAsync(rowcnt, 0, (NN + 4) * sizeof(int), 0);
    cudaMemsetAsync(colcnt, 0, NN * sizeof(int), 0);
    k_hist<<<(e / 4 + 255) / 256, 256>>>(row, col, e);
    k_scan_partial<<<nb, 256>>>(n);
    k_scan_bsums<<<1, 128>>>(nb, n);
    k_scan_add_dinv<<<(n + 255) / 256, 256>>>(n);
    k_fill<<<(e + 255) / 256, 256>>>(row, col, e);

    // Join
    cudaStreamWaitEvent(0, evJoin, 0);

    // Layer 0 aggregation (applies dinv[j] per neighbor, dinv[i] outer, relu)
    k_gather<0><<<gath_blocks, 256>>>(hs, aggh, n);

    // Layer 1
    k_gemm<false, true><<<gemm_blocks, 256>>>(aggh, w1h, b1, hs, n);
    k_gather<1><<<gath_blocks, 256>>>(hs, out, n);
}